// round 4
// baseline (speedup 1.0000x reference)
#include <cuda_runtime.h>

#define NROWS 100000
#define INDIM 256
#define HID   64
#define OUTD  64

// scratch (device globals: no allocation allowed)
__device__ __align__(16) float g_H[(size_t)NROWS * HID];
__device__ __align__(16) float g_O[(size_t)NROWS * OUTD];

// ---------------------------------------------------------------------------
// Kernel 1: H = X @ W1   (100000x256 @ 256x64)
// 512 threads, grid-stride over 64-row tiles. W1 (64KB) + X tile (64KB) smem.
// Thread t: cols c4 = (t&15)*4, rows rg = (t>>4)*2  -> 2x4 register block.
// 16 warps/SM (4 per SMSP) to hide LDS latency; X loads warp-broadcast.
// ---------------------------------------------------------------------------
__global__ void __launch_bounds__(512, 1) gemm1_kernel(
    const float* __restrict__ X, const float* __restrict__ W1,
    float* __restrict__ H)
{
    extern __shared__ float smem[];
    float* Ws = smem;                 // [256*64]  64KB
    float* Xs = smem + INDIM * HID;   // [64*256]  64KB

    const int tid = threadIdx.x;

    // load W1 once (vectorized)
    {
        const float4* src = reinterpret_cast<const float4*>(W1);
        float4* dst = reinterpret_cast<float4*>(Ws);
        #pragma unroll
        for (int i = tid; i < (INDIM * HID) / 4; i += 512) dst[i] = src[i];
    }

    const int c4 = (tid & 15) * 4;      // 0,4,..,60
    const int rg = (tid >> 4) * 2;      // 0,2,..,62
    const int ntiles = (NROWS + 63) / 64;   // 1563 (last tile: 32 rows)

    for (int tile = blockIdx.x; tile < ntiles; tile += gridDim.x) {
        const int rowBase = tile * 64;
        const int rowsIn  = NROWS - rowBase;

        __syncthreads();  // Xs free to overwrite (also covers Ws on 1st iter)
        {
            const float4* src =
                reinterpret_cast<const float4*>(X + (size_t)rowBase * INDIM);
            float4* dst = reinterpret_cast<float4*>(Xs);
            #pragma unroll
            for (int i = tid; i < (64 * INDIM) / 4; i += 512) {
                const int r = i >> 6;   // 64 float4 per row
                dst[i] = (r < rowsIn) ? src[i] : make_float4(0.f, 0.f, 0.f, 0.f);
            }
        }
        __syncthreads();

        float acc[2][4];
        #pragma unroll
        for (int r = 0; r < 2; ++r)
            #pragma unroll
            for (int c = 0; c < 4; ++c) acc[r][c] = 0.f;

        const float* xs = Xs + rg * INDIM;

        #pragma unroll 8
        for (int k = 0; k < INDIM; k += 4) {
            float4 w[4];
            #pragma unroll
            for (int j = 0; j < 4; ++j)
                w[j] = *reinterpret_cast<const float4*>(Ws + (k + j) * HID + c4);

            #pragma unroll
            for (int r = 0; r < 2; ++r) {
                const float4 x = *reinterpret_cast<const float4*>(xs + r * INDIM + k);
                acc[r][0] += x.x * w[0].x + x.y * w[1].x + x.z * w[2].x + x.w * w[3].x;
                acc[r][1] += x.x * w[0].y + x.y * w[1].y + x.z * w[2].y + x.w * w[3].y;
                acc[r][2] += x.x * w[0].z + x.y * w[1].z + x.z * w[2].z + x.w * w[3].z;
                acc[r][3] += x.x * w[0].w + x.y * w[1].w + x.z * w[2].w + x.w * w[3].w;
            }
        }

        #pragma unroll
        for (int r = 0; r < 2; ++r) {
            const int row = rowBase + rg + r;
            if (rg + r < rowsIn) {
                *reinterpret_cast<float4*>(H + (size_t)row * HID + c4) =
                    make_float4(acc[r][0], acc[r][1], acc[r][2], acc[r][3]);
            }
        }
    }
}

// ---------------------------------------------------------------------------
// Kernel 2 (fused): O = relu(A @ H) @ W2
// Warp per row. Row metadata loaded with 2 coalesced LDGs + shfl broadcast.
// ---------------------------------------------------------------------------
__global__ void __launch_bounds__(256) spmm_relu_gemm2_kernel(
    const float* __restrict__ H, const float* __restrict__ W2,
    const float* __restrict__ vals, const int* __restrict__ rowptr,
    const int* __restrict__ colind, float* __restrict__ O)
{
    __shared__ float W2s[HID * OUTD];   // 16KB
    __shared__ float Hs[8][HID];        // per-warp staging

    const int tid = threadIdx.x;
    {
        const float4* src = reinterpret_cast<const float4*>(W2);
        float4* dst = reinterpret_cast<float4*>(W2s);
        #pragma unroll
        for (int i = tid; i < (HID * OUTD) / 4; i += 256) dst[i] = src[i];
    }
    __syncthreads();

    const int warp = tid >> 5;
    const int lane = tid & 31;
    const int row  = blockIdx.x * 8 + warp;
    if (row >= NROWS) return;

    const int start = rowptr[row];
    const int deg   = rowptr[row + 1] - start;

    float ax = 0.f, ay = 0.f;
    if (deg == 16) {
        // coalesced metadata fetch: 2 LDG wavefronts instead of 32 broadcasts
        const int   myc = (lane < 16) ? __ldg(colind + start + lane) : 0;
        const float myv = (lane < 16) ? __ldg(vals + start + lane) : 0.f;
        #pragma unroll
        for (int e = 0; e < 16; ++e) {
            const int   col = __shfl_sync(0xffffffffu, myc, e);
            const float v   = __shfl_sync(0xffffffffu, myv, e);
            const float2 h  =
                *reinterpret_cast<const float2*>(H + (size_t)col * HID + 2 * lane);
            ax += v * h.x;
            ay += v * h.y;
        }
    } else {
        for (int e = start; e < start + deg; ++e) {
            const int   col = colind[e];
            const float v   = vals[e];
            const float2 h  =
                *reinterpret_cast<const float2*>(H + (size_t)col * HID + 2 * lane);
            ax += v * h.x;
            ay += v * h.y;
        }
    }
    ax = fmaxf(ax, 0.f);
    ay = fmaxf(ay, 0.f);

    Hs[warp][2 * lane]     = ax;
    Hs[warp][2 * lane + 1] = ay;
    __syncwarp();

    float ox = 0.f, oy = 0.f;
    #pragma unroll
    for (int j = 0; j < HID; ++j) {
        const float a = Hs[warp][j];
        const float2 w =
            *reinterpret_cast<const float2*>(W2s + j * OUTD + 2 * lane);
        ox += a * w.x;
        oy += a * w.y;
    }

    *reinterpret_cast<float2*>(O + (size_t)row * OUTD + 2 * lane) =
        make_float2(ox, oy);
}

// ---------------------------------------------------------------------------
// Kernel 3: out = A @ O
// ---------------------------------------------------------------------------
__global__ void __launch_bounds__(256) spmm2_kernel(
    const float* __restrict__ O, const float* __restrict__ vals,
    const int* __restrict__ rowptr, const int* __restrict__ colind,
    float* __restrict__ out)
{
    const int tid  = threadIdx.x;
    const int warp = tid >> 5;
    const int lane = tid & 31;
    const int row  = blockIdx.x * 8 + warp;
    if (row >= NROWS) return;

    const int start = rowptr[row];
    const int deg   = rowptr[row + 1] - start;

    float ax = 0.f, ay = 0.f;
    if (deg == 16) {
        const int   myc = (lane < 16) ? __ldg(colind + start + lane) : 0;
        const float myv = (lane < 16) ? __ldg(vals + start + lane) : 0.f;
        #pragma unroll
        for (int e = 0; e < 16; ++e) {
            const int   col = __shfl_sync(0xffffffffu, myc, e);
            const float v   = __shfl_sync(0xffffffffu, myv, e);
            const float2 o  =
                *reinterpret_cast<const float2*>(O + (size_t)col * OUTD + 2 * lane);
            ax += v * o.x;
            ay += v * o.y;
        }
    } else {
        for (int e = start; e < start + deg; ++e) {
            const int   col = colind[e];
            const float v   = vals[e];
            const float2 o  =
                *reinterpret_cast<const float2*>(O + (size_t)col * OUTD + 2 * lane);
            ax += v * o.x;
            ay += v * o.y;
        }
    }

    *reinterpret_cast<float2*>(out + (size_t)row * OUTD + 2 * lane) =
        make_float2(ax, ay);
}

// ---------------------------------------------------------------------------
extern "C" void kernel_launch(void* const* d_in, const int* in_sizes, int n_in,
                              void* d_out, int out_size)
{
    const float* X      = (const float*)d_in[0];
    const float* W1     = (const float*)d_in[1];
    const float* W2     = (const float*)d_in[2];
    const float* vals   = (const float*)d_in[3];
    const int*   rowptr = (const int*)d_in[4];
    const int*   colind = (const int*)d_in[5];
    float*       out    = (float*)d_out;

    float* H; cudaGetSymbolAddress((void**)&H, g_H);
    float* O; cudaGetSymbolAddress((void**)&O, g_O);

    const int smem1 = (INDIM * HID + 64 * INDIM) * sizeof(float);  // 128KB
    static bool attr_set = false;
    if (!attr_set) {
        cudaFuncSetAttribute(gemm1_kernel,
                             cudaFuncAttributeMaxDynamicSharedMemorySize, smem1);
        attr_set = true;
    }

    gemm1_kernel<<<148, 512, smem1>>>(X, W1, H);
    spmm_relu_gemm2_kernel<<<(NROWS + 7) / 8, 256>>>(H, W2, vals, rowptr,
                                                     colind, O);
    spmm2_kernel<<<(NROWS + 7) / 8, 256>>>(O, vals, rowptr, colind, out);
}

// round 5
// speedup vs baseline: 1.0753x; 1.0753x over previous
#include <cuda_runtime.h>

#define NROWS 100000
#define INDIM 256
#define HID   64
#define OUTD  64

// scratch (device globals: no allocation allowed)
__device__ __align__(16) float g_H[(size_t)NROWS * HID];
__device__ __align__(16) float g_O[(size_t)NROWS * OUTD];

// packed f32x2 helpers (Blackwell sm_103a)
#define FMA_F32X2(d, a, b, c) \
    asm("fma.rn.f32x2 %0, %1, %2, %3;" : "=l"(d) : "l"(a), "l"(b), "l"(c))
#define PACK_F32X2(out, lo, hi) \
    asm("mov.b64 %0, {%1, %2};" : "=l"(out) : "f"(lo), "f"(hi))
#define UNPACK_F32X2(lo, hi, in) \
    asm("mov.b64 {%0, %1}, %2;" : "=f"(lo), "=f"(hi) : "l"(in))

// ---------------------------------------------------------------------------
// Kernel 1: H = X @ W1   (100000x256 @ 256x64), fp32 via packed FFMA2.
// 256 threads, grid-stride over 64-row tiles; W1 (64KB) + X tile (64KB) smem.
// Thread t: cols c4=(t&15)*4, rows rg=(t>>4)*4 -> 4x4 block.
// f32x2 pairs run along k: acc[r][c] = (sum over even k, sum over odd k),
// reduced at the end. X pairs come free from float4 LDS; W pairs need
// 8 mov.b64 per 4-k chunk. 32 FFMA2 per chunk replaces 64 FFMA (rt=2 pipe).
// ---------------------------------------------------------------------------
__global__ void __launch_bounds__(256, 1) gemm1_kernel(
    const float* __restrict__ X, const float* __restrict__ W1,
    float* __restrict__ H)
{
    extern __shared__ float smem[];
    float* Ws = smem;                 // [256*64]  64KB
    float* Xs = smem + INDIM * HID;   // [64*256]  64KB

    const int tid = threadIdx.x;

    // load W1 once
    {
        const float4* src = reinterpret_cast<const float4*>(W1);
        float4* dst = reinterpret_cast<float4*>(Ws);
        #pragma unroll
        for (int i = tid; i < (INDIM * HID) / 4; i += 256) dst[i] = src[i];
    }

    const int c4 = (tid & 15) * 4;      // 0,4,..,60
    const int rg = (tid >> 4) * 4;      // 0,4,..,60
    const int ntiles = (NROWS + 63) / 64;   // 1563 (last tile: 32 rows)

    for (int tile = blockIdx.x; tile < ntiles; tile += gridDim.x) {
        const int rowBase = tile * 64;
        const int rowsIn  = NROWS - rowBase;

        __syncthreads();
        {
            const float4* src =
                reinterpret_cast<const float4*>(X + (size_t)rowBase * INDIM);
            float4* dst = reinterpret_cast<float4*>(Xs);
            #pragma unroll
            for (int i = tid; i < (64 * INDIM) / 4; i += 256) {
                const int r = i >> 6;   // 64 float4 per row
                dst[i] = (r < rowsIn) ? src[i] : make_float4(0.f, 0.f, 0.f, 0.f);
            }
        }
        __syncthreads();

        unsigned long long acc[4][4];   // [row][col] : (even-k, odd-k) partials
        #pragma unroll
        for (int r = 0; r < 4; ++r)
            #pragma unroll
            for (int c = 0; c < 4; ++c) acc[r][c] = 0ull;

        const float* xs = Xs + rg * INDIM;

        #pragma unroll 8
        for (int k = 0; k < INDIM; k += 4) {
            const float4 wa = *reinterpret_cast<const float4*>(Ws + (k + 0) * HID + c4);
            const float4 wb = *reinterpret_cast<const float4*>(Ws + (k + 1) * HID + c4);
            const float4 wc = *reinterpret_cast<const float4*>(Ws + (k + 2) * HID + c4);
            const float4 wd = *reinterpret_cast<const float4*>(Ws + (k + 3) * HID + c4);

            unsigned long long p0[4], p1[4];
            PACK_F32X2(p0[0], wa.x, wb.x);
            PACK_F32X2(p0[1], wa.y, wb.y);
            PACK_F32X2(p0[2], wa.z, wb.z);
            PACK_F32X2(p0[3], wa.w, wb.w);
            PACK_F32X2(p1[0], wc.x, wd.x);
            PACK_F32X2(p1[1], wc.y, wd.y);
            PACK_F32X2(p1[2], wc.z, wd.z);
            PACK_F32X2(p1[3], wc.w, wd.w);

            #pragma unroll
            for (int r = 0; r < 4; ++r) {
                const float4 x = *reinterpret_cast<const float4*>(xs + r * INDIM + k);
                unsigned long long x01, x23;
                PACK_F32X2(x01, x.x, x.y);   // adjacent regs: folds away
                PACK_F32X2(x23, x.z, x.w);
                #pragma unroll
                for (int c = 0; c < 4; ++c) {
                    FMA_F32X2(acc[r][c], x01, p0[c], acc[r][c]);
                    FMA_F32X2(acc[r][c], x23, p1[c], acc[r][c]);
                }
            }
        }

        #pragma unroll
        for (int r = 0; r < 4; ++r) {
            if (rg + r < rowsIn) {
                const int row = rowBase + rg + r;
                float4 o;
                float lo, hi;
                UNPACK_F32X2(lo, hi, acc[r][0]); o.x = lo + hi;
                UNPACK_F32X2(lo, hi, acc[r][1]); o.y = lo + hi;
                UNPACK_F32X2(lo, hi, acc[r][2]); o.z = lo + hi;
                UNPACK_F32X2(lo, hi, acc[r][3]); o.w = lo + hi;
                *reinterpret_cast<float4*>(H + (size_t)row * HID + c4) = o;
            }
        }
    }
}

// ---------------------------------------------------------------------------
// Kernel 2 (fused): O = relu(A @ H) @ W2
// Persistent blocks (grid-stride): W2 loaded once per block, not per row-tile.
// ---------------------------------------------------------------------------
__global__ void __launch_bounds__(256) spmm_relu_gemm2_kernel(
    const float* __restrict__ H, const float* __restrict__ W2,
    const float* __restrict__ vals, const int* __restrict__ rowptr,
    const int* __restrict__ colind, float* __restrict__ O)
{
    __shared__ float W2s[HID * OUTD];   // 16KB
    __shared__ float Hs[8][HID];

    const int tid = threadIdx.x;
    {
        const float4* src = reinterpret_cast<const float4*>(W2);
        float4* dst = reinterpret_cast<float4*>(W2s);
        #pragma unroll
        for (int i = tid; i < (HID * OUTD) / 4; i += 256) dst[i] = src[i];
    }
    __syncthreads();

    const int warp   = tid >> 5;
    const int lane   = tid & 31;
    const int stride = gridDim.x * 8;

    for (int row = blockIdx.x * 8 + warp; row < NROWS; row += stride) {
        const int start = rowptr[row];
        const int deg   = rowptr[row + 1] - start;

        float ax = 0.f, ay = 0.f;
        if (deg == 16) {
            const int   myc = (lane < 16) ? __ldg(colind + start + lane) : 0;
            const float myv = (lane < 16) ? __ldg(vals + start + lane) : 0.f;
            #pragma unroll
            for (int e = 0; e < 16; ++e) {
                const int   col = __shfl_sync(0xffffffffu, myc, e);
                const float v   = __shfl_sync(0xffffffffu, myv, e);
                const float2 h  =
                    *reinterpret_cast<const float2*>(H + (size_t)col * HID + 2 * lane);
                ax += v * h.x;
                ay += v * h.y;
            }
        } else {
            for (int e = start; e < start + deg; ++e) {
                const int   col = colind[e];
                const float v   = vals[e];
                const float2 h  =
                    *reinterpret_cast<const float2*>(H + (size_t)col * HID + 2 * lane);
                ax += v * h.x;
                ay += v * h.y;
            }
        }
        ax = fmaxf(ax, 0.f);
        ay = fmaxf(ay, 0.f);

        Hs[warp][2 * lane]     = ax;
        Hs[warp][2 * lane + 1] = ay;
        __syncwarp();

        float ox = 0.f, oy = 0.f;
        #pragma unroll
        for (int j = 0; j < HID; ++j) {
            const float a = Hs[warp][j];
            const float2 w =
                *reinterpret_cast<const float2*>(W2s + j * OUTD + 2 * lane);
            ox += a * w.x;
            oy += a * w.y;
        }
        __syncwarp();

        *reinterpret_cast<float2*>(O + (size_t)row * OUTD + 2 * lane) =
            make_float2(ox, oy);
    }
}

// ---------------------------------------------------------------------------
// Kernel 3: out = A @ O   (persistent grid-stride)
// ---------------------------------------------------------------------------
__global__ void __launch_bounds__(256) spmm2_kernel(
    const float* __restrict__ O, const float* __restrict__ vals,
    const int* __restrict__ rowptr, const int* __restrict__ colind,
    float* __restrict__ out)
{
    const int tid    = threadIdx.x;
    const int warp   = tid >> 5;
    const int lane   = tid & 31;
    const int stride = gridDim.x * 8;

    for (int row = blockIdx.x * 8 + warp; row < NROWS; row += stride) {
        const int start = rowptr[row];
        const int deg   = rowptr[row + 1] - start;

        float ax = 0.f, ay = 0.f;
        if (deg == 16) {
            const int   myc = (lane < 16) ? __ldg(colind + start + lane) : 0;
            const float myv = (lane < 16) ? __ldg(vals + start + lane) : 0.f;
            #pragma unroll
            for (int e = 0; e < 16; ++e) {
                const int   col = __shfl_sync(0xffffffffu, myc, e);
                const float v   = __shfl_sync(0xffffffffu, myv, e);
                const float2 o  =
                    *reinterpret_cast<const float2*>(O + (size_t)col * OUTD + 2 * lane);
                ax += v * o.x;
                ay += v * o.y;
            }
        } else {
            for (int e = start; e < start + deg; ++e) {
                const int   col = colind[e];
                const float v   = vals[e];
                const float2 o  =
                    *reinterpret_cast<const float2*>(O + (size_t)col * OUTD + 2 * lane);
                ax += v * o.x;
                ay += v * o.y;
            }
        }

        *reinterpret_cast<float2*>(out + (size_t)row * OUTD + 2 * lane) =
            make_float2(ax, ay);
    }
}

// ---------------------------------------------------------------------------
extern "C" void kernel_launch(void* const* d_in, const int* in_sizes, int n_in,
                              void* d_out, int out_size)
{
    const float* X      = (const float*)d_in[0];
    const float* W1     = (const float*)d_in[1];
    const float* W2     = (const float*)d_in[2];
    const float* vals   = (const float*)d_in[3];
    const int*   rowptr = (const int*)d_in[4];
    const int*   colind = (const int*)d_in[5];
    float*       out    = (float*)d_out;

    float* H; cudaGetSymbolAddress((void**)&H, g_H);
    float* O; cudaGetSymbolAddress((void**)&O, g_O);

    const int smem1 = (INDIM * HID + 64 * INDIM) * sizeof(float);  // 128KB
    static bool attr_set = false;
    if (!attr_set) {
        cudaFuncSetAttribute(gemm1_kernel,
                             cudaFuncAttributeMaxDynamicSharedMemorySize, smem1);
        attr_set = true;
    }

    gemm1_kernel<<<148, 256, smem1>>>(X, W1, H);
    spmm_relu_gemm2_kernel<<<1184, 256>>>(H, W2, vals, rowptr, colind, O);
    spmm2_kernel<<<1184, 256>>>(O, vals, rowptr, colind, out);
}

// round 7
// speedup vs baseline: 1.4055x; 1.3071x over previous
#include <cuda_runtime.h>
#include <cuda_bf16.h>
#include <cstdint>

#define NROWS 100000
#define INDIM 256
#define HID   64
#define OUTD  64

// scratch (device globals: no allocation allowed)
__device__ __align__(16) float g_H[(size_t)NROWS * HID];
__device__ __align__(16) float g_O[(size_t)NROWS * OUTD];

// m16n8k16 bf16 MMA, f32 accumulate (baseline PTX, works on .target sm_103)
#define MMA_BF16(c0, c1, c2, c3, a0, a1, a2, a3, b0, b1)                      \
    asm volatile(                                                             \
        "mma.sync.aligned.m16n8k16.row.col.f32.bf16.bf16.f32 "                \
        "{%0,%1,%2,%3}, {%4,%5,%6,%7}, {%8,%9}, {%0,%1,%2,%3};"               \
        : "+f"(c0), "+f"(c1), "+f"(c2), "+f"(c3)                              \
        : "r"(a0), "r"(a1), "r"(a2), "r"(a3), "r"(b0), "r"(b1))

// split a float2 into packed bf16x2 hi + bf16x2 lo (residual)
__device__ __forceinline__ void cvt_split(float2 v, uint32_t& hi, uint32_t& lo) {
    uint32_t h;
    asm("cvt.rn.bf16x2.f32 %0, %1, %2;" : "=r"(h) : "f"(v.y), "f"(v.x));
    const float h0 = __uint_as_float(h << 16);
    const float h1 = __uint_as_float(h & 0xffff0000u);
    const float r0 = v.x - h0;
    const float r1 = v.y - h1;
    uint32_t l;
    asm("cvt.rn.bf16x2.f32 %0, %1, %2;" : "=r"(l) : "f"(r1), "f"(r0));
    hi = h;
    lo = l;
}

#define BSTRIDE 264   // 256 + 8 bf16 padding -> conflict-free B-fragment LDS

// ---------------------------------------------------------------------------
// Kernel 1: H = X @ W1 via warp-level bf16 MMA, split-2 (3 MMAs), f32 accum.
// Block 256 thr = 8 warps x 32 rows = 256-row tile, one tile per block.
// A fragments: coalesced float2 LDG straight from X + in-register split.
// B (W1): converted once per block to smem, n-major [64][BSTRIDE] hi+lo.
// ---------------------------------------------------------------------------
__global__ void __launch_bounds__(256) gemm1_mma_kernel(
    const float* __restrict__ X, const float* __restrict__ W1,
    float* __restrict__ H)
{
    extern __shared__ __nv_bfloat16 wsm[];
    __nv_bfloat16* Bhi = wsm;                 // [64][BSTRIDE]
    __nv_bfloat16* Blo = wsm + 64 * BSTRIDE;  // [64][BSTRIDE]

    const int tid = threadIdx.x;

    // convert W1 (k-major [256][64]) -> smem n-major hi/lo
    for (int idx = tid; idx < INDIM * HID; idx += 256) {
        const int k = idx >> 6;
        const int n = idx & 63;
        const float w = W1[idx];
        const __nv_bfloat16 hb = __float2bfloat16(w);
        const float hf = __bfloat162float(hb);
        Bhi[n * BSTRIDE + k] = hb;
        Blo[n * BSTRIDE + k] = __float2bfloat16(w - hf);
    }
    __syncthreads();

    const int warp  = tid >> 5;
    const int lane  = tid & 31;
    const int rbase = blockIdx.x * 256 + warp * 32;
    if (rbase >= NROWS) return;

    const int rq = lane >> 2;         // 0..7
    const int cq = (lane & 3) * 2;    // 0,2,4,6

    float acc[2][8][4];
    #pragma unroll
    for (int m = 0; m < 2; ++m)
        #pragma unroll
        for (int n = 0; n < 8; ++n)
            #pragma unroll
            for (int i = 0; i < 4; ++i) acc[m][n][i] = 0.f;

    #pragma unroll 4
    for (int ks = 0; ks < 16; ++ks) {
        const int kb = ks * 16;
        uint32_t ahi[2][4], alo[2][4];

        #pragma unroll
        for (int m = 0; m < 2; ++m) {
            const int r0 = rbase + m * 16 + rq;
            const int r1 = r0 + 8;
            const float2 z = make_float2(0.f, 0.f);
            const float2 L0 = (r0 < NROWS)
                ? *reinterpret_cast<const float2*>(X + (size_t)r0 * INDIM + kb + cq) : z;
            const float2 L1 = (r1 < NROWS)
                ? *reinterpret_cast<const float2*>(X + (size_t)r1 * INDIM + kb + cq) : z;
            const float2 L2 = (r0 < NROWS)
                ? *reinterpret_cast<const float2*>(X + (size_t)r0 * INDIM + kb + cq + 8) : z;
            const float2 L3 = (r1 < NROWS)
                ? *reinterpret_cast<const float2*>(X + (size_t)r1 * INDIM + kb + cq + 8) : z;
            cvt_split(L0, ahi[m][0], alo[m][0]);
            cvt_split(L1, ahi[m][1], alo[m][1]);
            cvt_split(L2, ahi[m][2], alo[m][2]);
            cvt_split(L3, ahi[m][3], alo[m][3]);
        }

        #pragma unroll
        for (int n = 0; n < 8; ++n) {
            const int boff = (n * 8 + rq) * BSTRIDE + kb + cq;
            const uint32_t bh0 = *reinterpret_cast<const uint32_t*>(Bhi + boff);
            const uint32_t bh1 = *reinterpret_cast<const uint32_t*>(Bhi + boff + 8);
            const uint32_t bl0 = *reinterpret_cast<const uint32_t*>(Blo + boff);
            const uint32_t bl1 = *reinterpret_cast<const uint32_t*>(Blo + boff + 8);

            #pragma unroll
            for (int m = 0; m < 2; ++m) {
                MMA_BF16(acc[m][n][0], acc[m][n][1], acc[m][n][2], acc[m][n][3],
                         ahi[m][0], ahi[m][1], ahi[m][2], ahi[m][3], bh0, bh1);
                MMA_BF16(acc[m][n][0], acc[m][n][1], acc[m][n][2], acc[m][n][3],
                         ahi[m][0], ahi[m][1], ahi[m][2], ahi[m][3], bl0, bl1);
                MMA_BF16(acc[m][n][0], acc[m][n][1], acc[m][n][2], acc[m][n][3],
                         alo[m][0], alo[m][1], alo[m][2], alo[m][3], bh0, bh1);
            }
        }
    }

    #pragma unroll
    for (int m = 0; m < 2; ++m) {
        const int r0 = rbase + m * 16 + rq;
        const int r1 = r0 + 8;
        #pragma unroll
        for (int n = 0; n < 8; ++n) {
            const int col = n * 8 + cq;
            if (r0 < NROWS)
                *reinterpret_cast<float2*>(H + (size_t)r0 * HID + col) =
                    make_float2(acc[m][n][0], acc[m][n][1]);
            if (r1 < NROWS)
                *reinterpret_cast<float2*>(H + (size_t)r1 * HID + col) =
                    make_float2(acc[m][n][2], acc[m][n][3]);
        }
    }
}

// ---------------------------------------------------------------------------
// Kernel 2 (fused): O = relu(A @ H) @ W2   (round-2 proven variant)
// ---------------------------------------------------------------------------
__global__ void __launch_bounds__(256) spmm_relu_gemm2_kernel(
    const float* __restrict__ H, const float* __restrict__ W2,
    const float* __restrict__ vals, const int* __restrict__ rowptr,
    const int* __restrict__ colind, float* __restrict__ O)
{
    __shared__ float W2s[HID * OUTD];
    __shared__ float Hs[8][HID];

    const int tid = threadIdx.x;
    {
        const float4* src = reinterpret_cast<const float4*>(W2);
        float4* dst = reinterpret_cast<float4*>(W2s);
        #pragma unroll
        for (int i = tid; i < (HID * OUTD) / 4; i += 256) dst[i] = src[i];
    }
    __syncthreads();

    const int warp = tid >> 5;
    const int lane = tid & 31;
    const int row  = blockIdx.x * 8 + warp;
    if (row >= NROWS) return;

    const int start = rowptr[row];
    const int deg   = rowptr[row + 1] - start;

    float ax = 0.f, ay = 0.f;
    if (deg == 16) {
        #pragma unroll
        for (int e = 0; e < 16; ++e) {
            const int   col = __ldg(colind + start + e);
            const float v   = __ldg(vals + start + e);
            const float2 h  =
                *reinterpret_cast<const float2*>(H + (size_t)col * HID + 2 * lane);
            ax += v * h.x;
            ay += v * h.y;
        }
    } else {
        for (int e = start; e < start + deg; ++e) {
            const int   col = colind[e];
            const float v   = vals[e];
            const float2 h  =
                *reinterpret_cast<const float2*>(H + (size_t)col * HID + 2 * lane);
            ax += v * h.x;
            ay += v * h.y;
        }
    }
    ax = fmaxf(ax, 0.f);
    ay = fmaxf(ay, 0.f);

    Hs[warp][2 * lane]     = ax;
    Hs[warp][2 * lane + 1] = ay;
    __syncwarp();

    float ox = 0.f, oy = 0.f;
    #pragma unroll
    for (int j = 0; j < HID; ++j) {
        const float a = Hs[warp][j];
        const float2 w =
            *reinterpret_cast<const float2*>(W2s + j * OUTD + 2 * lane);
        ox += a * w.x;
        oy += a * w.y;
    }

    *reinterpret_cast<float2*>(O + (size_t)row * OUTD + 2 * lane) =
        make_float2(ox, oy);
}

// ---------------------------------------------------------------------------
// Kernel 3: out = A @ O   (round-2 proven variant)
// ---------------------------------------------------------------------------
__global__ void __launch_bounds__(256) spmm2_kernel(
    const float* __restrict__ O, const float* __restrict__ vals,
    const int* __restrict__ rowptr, const int* __restrict__ colind,
    float* __restrict__ out)
{
    const int tid  = threadIdx.x;
    const int warp = tid >> 5;
    const int lane = tid & 31;
    const int row  = blockIdx.x * 8 + warp;
    if (row >= NROWS) return;

    const int start = rowptr[row];
    const int deg   = rowptr[row + 1] - start;

    float ax = 0.f, ay = 0.f;
    if (deg == 16) {
        #pragma unroll
        for (int e = 0; e < 16; ++e) {
            const int   col = __ldg(colind + start + e);
            const float v   = __ldg(vals + start + e);
            const float2 o  =
                *reinterpret_cast<const float2*>(O + (size_t)col * OUTD + 2 * lane);
            ax += v * o.x;
            ay += v * o.y;
        }
    } else {
        for (int e = start; e < start + deg; ++e) {
            const int   col = colind[e];
            const float v   = vals[e];
            const float2 o  =
                *reinterpret_cast<const float2*>(O + (size_t)col * OUTD + 2 * lane);
            ax += v * o.x;
            ay += v * o.y;
        }
    }

    *reinterpret_cast<float2*>(out + (size_t)row * OUTD + 2 * lane) =
        make_float2(ax, ay);
}

// ---------------------------------------------------------------------------
extern "C" void kernel_launch(void* const* d_in, const int* in_sizes, int n_in,
                              void* d_out, int out_size)
{
    const float* X      = (const float*)d_in[0];
    const float* W1     = (const float*)d_in[1];
    const float* W2     = (const float*)d_in[2];
    const float* vals   = (const float*)d_in[3];
    const int*   rowptr = (const int*)d_in[4];
    const int*   colind = (const int*)d_in[5];
    float*       out    = (float*)d_out;

    float* H; cudaGetSymbolAddress((void**)&H, g_H);
    float* O; cudaGetSymbolAddress((void**)&O, g_O);

    const int smem1 = 2 * 64 * BSTRIDE * sizeof(__nv_bfloat16);  // 67584 B
    static bool attr_set = false;
    if (!attr_set) {
        cudaFuncSetAttribute(gemm1_mma_kernel,
                             cudaFuncAttributeMaxDynamicSharedMemorySize, smem1);
        attr_set = true;
    }

    gemm1_mma_kernel<<<(NROWS + 255) / 256, 256, smem1>>>(X, W1, H);
    spmm_relu_gemm2_kernel<<<(NROWS + 7) / 8, 256>>>(H, W2, vals, rowptr,
                                                     colind, O);
    spmm2_kernel<<<(NROWS + 7) / 8, 256>>>(O, vals, rowptr, colind, out);
}

// round 8
// speedup vs baseline: 1.5958x; 1.1353x over previous
#include <cuda_runtime.h>
#include <cuda_bf16.h>
#include <cstdint>

#define NROWS 100000
#define INDIM 256
#define HID   64
#define OUTD  64

// scratch (device globals: no allocation allowed)
__device__ __align__(16) float g_H[(size_t)NROWS * HID];
__device__ __align__(16) float g_O[(size_t)NROWS * OUTD];

// m16n8k16 bf16 MMA, f32 accumulate (baseline PTX, works on .target sm_103)
#define MMA_BF16(c0, c1, c2, c3, a0, a1, a2, a3, b0, b1)                      \
    asm volatile(                                                             \
        "mma.sync.aligned.m16n8k16.row.col.f32.bf16.bf16.f32 "                \
        "{%0,%1,%2,%3}, {%4,%5,%6,%7}, {%8,%9}, {%0,%1,%2,%3};"               \
        : "+f"(c0), "+f"(c1), "+f"(c2), "+f"(c3)                              \
        : "r"(a0), "r"(a1), "r"(a2), "r"(a3), "r"(b0), "r"(b1))

// split a float2 into packed bf16x2 hi + bf16x2 lo (residual)
__device__ __forceinline__ void cvt_split(float2 v, uint32_t& hi, uint32_t& lo) {
    uint32_t h;
    asm("cvt.rn.bf16x2.f32 %0, %1, %2;" : "=r"(h) : "f"(v.y), "f"(v.x));
    const float h0 = __uint_as_float(h << 16);
    const float h1 = __uint_as_float(h & 0xffff0000u);
    const float r0 = v.x - h0;
    const float r1 = v.y - h1;
    uint32_t l;
    asm("cvt.rn.bf16x2.f32 %0, %1, %2;" : "=r"(l) : "f"(r1), "f"(r0));
    hi = h;
    lo = l;
}

#define BSTRIDE 264   // 256 + 8 bf16 padding -> conflict-free B-fragment LDS

// ---------------------------------------------------------------------------
// Kernel 1: H = X @ W1 via warp-level bf16 MMA, split-2 (3 MMAs), f32 accum.
// Block 256 thr = 8 warps x 32 rows = 256-row tile.
// A fragments double-buffered: LDGs for k-step s+1 issued before MMAs of s.
// ---------------------------------------------------------------------------
__global__ void __launch_bounds__(256) gemm1_mma_kernel(
    const float* __restrict__ X, const float* __restrict__ W1,
    float* __restrict__ H)
{
    extern __shared__ __nv_bfloat16 wsm[];
    __nv_bfloat16* Bhi = wsm;                 // [64][BSTRIDE]
    __nv_bfloat16* Blo = wsm + 64 * BSTRIDE;  // [64][BSTRIDE]

    const int tid = threadIdx.x;

    // convert W1 (k-major [256][64]) -> smem n-major hi/lo
    for (int idx = tid; idx < INDIM * HID; idx += 256) {
        const int k = idx >> 6;
        const int n = idx & 63;
        const float w = W1[idx];
        const __nv_bfloat16 hb = __float2bfloat16(w);
        const float hf = __bfloat162float(hb);
        Bhi[n * BSTRIDE + k] = hb;
        Blo[n * BSTRIDE + k] = __float2bfloat16(w - hf);
    }
    __syncthreads();

    const int warp  = tid >> 5;
    const int lane  = tid & 31;
    const int rbase = blockIdx.x * 256 + warp * 32;
    if (rbase >= NROWS) return;

    const int rq = lane >> 2;         // 0..7
    const int cq = (lane & 3) * 2;    // 0,2,4,6

    // row pointers (clamped; results for clamped rows discarded at store)
    const int r00 = rbase + rq;
    const int r01 = r00 + 8;
    const int r10 = rbase + 16 + rq;
    const int r11 = r10 + 8;
    const float* px[2][2];
    px[0][0] = X + (size_t)min(r00, NROWS - 1) * INDIM;
    px[0][1] = X + (size_t)min(r01, NROWS - 1) * INDIM;
    px[1][0] = X + (size_t)min(r10, NROWS - 1) * INDIM;
    px[1][1] = X + (size_t)min(r11, NROWS - 1) * INDIM;

    float acc[2][8][4];
    #pragma unroll
    for (int m = 0; m < 2; ++m)
        #pragma unroll
        for (int n = 0; n < 8; ++n)
            #pragma unroll
            for (int i = 0; i < 4; ++i) acc[m][n][i] = 0.f;

    float2 fb[2][2][4];   // [buf][m][frag]

    // prime buffer 0 (k-step 0)
    #pragma unroll
    for (int m = 0; m < 2; ++m) {
        fb[0][m][0] = *reinterpret_cast<const float2*>(px[m][0] + cq);
        fb[0][m][1] = *reinterpret_cast<const float2*>(px[m][1] + cq);
        fb[0][m][2] = *reinterpret_cast<const float2*>(px[m][0] + cq + 8);
        fb[0][m][3] = *reinterpret_cast<const float2*>(px[m][1] + cq + 8);
    }

    #pragma unroll
    for (int ks = 0; ks < 16; ++ks) {
        const int cur = ks & 1;
        // prefetch next k-step into the other buffer
        if (ks < 15) {
            const int kb = (ks + 1) * 16;
            #pragma unroll
            for (int m = 0; m < 2; ++m) {
                fb[cur ^ 1][m][0] = *reinterpret_cast<const float2*>(px[m][0] + kb + cq);
                fb[cur ^ 1][m][1] = *reinterpret_cast<const float2*>(px[m][1] + kb + cq);
                fb[cur ^ 1][m][2] = *reinterpret_cast<const float2*>(px[m][0] + kb + cq + 8);
                fb[cur ^ 1][m][3] = *reinterpret_cast<const float2*>(px[m][1] + kb + cq + 8);
            }
        }

        // convert current buffer
        uint32_t ahi[2][4], alo[2][4];
        #pragma unroll
        for (int m = 0; m < 2; ++m) {
            cvt_split(fb[cur][m][0], ahi[m][0], alo[m][0]);
            cvt_split(fb[cur][m][1], ahi[m][1], alo[m][1]);
            cvt_split(fb[cur][m][2], ahi[m][2], alo[m][2]);
            cvt_split(fb[cur][m][3], ahi[m][3], alo[m][3]);
        }

        const int kb = ks * 16;
        #pragma unroll
        for (int n = 0; n < 8; ++n) {
            const int boff = (n * 8 + rq) * BSTRIDE + kb + cq;
            const uint32_t bh0 = *reinterpret_cast<const uint32_t*>(Bhi + boff);
            const uint32_t bh1 = *reinterpret_cast<const uint32_t*>(Bhi + boff + 8);
            const uint32_t bl0 = *reinterpret_cast<const uint32_t*>(Blo + boff);
            const uint32_t bl1 = *reinterpret_cast<const uint32_t*>(Blo + boff + 8);

            #pragma unroll
            for (int m = 0; m < 2; ++m) {
                MMA_BF16(acc[m][n][0], acc[m][n][1], acc[m][n][2], acc[m][n][3],
                         ahi[m][0], ahi[m][1], ahi[m][2], ahi[m][3], bh0, bh1);
                MMA_BF16(acc[m][n][0], acc[m][n][1], acc[m][n][2], acc[m][n][3],
                         ahi[m][0], ahi[m][1], ahi[m][2], ahi[m][3], bl0, bl1);
                MMA_BF16(acc[m][n][0], acc[m][n][1], acc[m][n][2], acc[m][n][3],
                         alo[m][0], alo[m][1], alo[m][2], alo[m][3], bh0, bh1);
            }
        }
    }

    #pragma unroll
    for (int m = 0; m < 2; ++m) {
        const int r0 = rbase + m * 16 + rq;
        const int r1 = r0 + 8;
        #pragma unroll
        for (int n = 0; n < 8; ++n) {
            const int col = n * 8 + cq;
            if (r0 < NROWS)
                *reinterpret_cast<float2*>(H + (size_t)r0 * HID + col) =
                    make_float2(acc[m][n][0], acc[m][n][1]);
            if (r1 < NROWS)
                *reinterpret_cast<float2*>(H + (size_t)r1 * HID + col) =
                    make_float2(acc[m][n][2], acc[m][n][3]);
        }
    }
}

// ---------------------------------------------------------------------------
// Kernel 2 (fused): O = relu(A @ H) @ W2
// 2 rows per warp: one coalesced metadata LDG serves both rows; 32 gathers
// in flight per warp.
// ---------------------------------------------------------------------------
__global__ void __launch_bounds__(256) spmm_relu_gemm2_kernel(
    const float* __restrict__ H, const float* __restrict__ W2,
    const float* __restrict__ vals, const int* __restrict__ rowptr,
    const int* __restrict__ colind, float* __restrict__ O)
{
    __shared__ float W2s[HID * OUTD];
    __shared__ float Hs[8][2][HID];

    const int tid = threadIdx.x;
    {
        const float4* src = reinterpret_cast<const float4*>(W2);
        float4* dst = reinterpret_cast<float4*>(W2s);
        #pragma unroll
        for (int i = tid; i < (HID * OUTD) / 4; i += 256) dst[i] = src[i];
    }
    __syncthreads();

    const int warp = tid >> 5;
    const int lane = tid & 31;
    const int row0 = (blockIdx.x * 8 + warp) * 2;
    const int row1 = row0 + 1;
    if (row0 >= NROWS) return;

    const int s0 = rowptr[row0];
    const int d0 = rowptr[row0 + 1] - s0;
    const int s1 = (row1 < NROWS) ? rowptr[row1] : 0;
    const int d1 = (row1 < NROWS) ? rowptr[row1 + 1] - s1 : 0;

    float ax0 = 0.f, ay0 = 0.f, ax1 = 0.f, ay1 = 0.f;

    if (d0 == 16 && d1 == 16 && s1 == s0 + 16) {
        // contiguous fixed-degree rows: one LDG covers both rows' metadata
        const int   myc = __ldg(colind + s0 + lane);
        const float myv = __ldg(vals + s0 + lane);
        #pragma unroll
        for (int e = 0; e < 16; ++e) {
            const int   c0 = __shfl_sync(0xffffffffu, myc, e);
            const float v0 = __shfl_sync(0xffffffffu, myv, e);
            const int   c1 = __shfl_sync(0xffffffffu, myc, 16 + e);
            const float v1 = __shfl_sync(0xffffffffu, myv, 16 + e);
            const float2 h0 =
                *reinterpret_cast<const float2*>(H + (size_t)c0 * HID + 2 * lane);
            const float2 h1 =
                *reinterpret_cast<const float2*>(H + (size_t)c1 * HID + 2 * lane);
            ax0 += v0 * h0.x;  ay0 += v0 * h0.y;
            ax1 += v1 * h1.x;  ay1 += v1 * h1.y;
        }
    } else {
        for (int e = s0; e < s0 + d0; ++e) {
            const int   col = colind[e];
            const float v   = vals[e];
            const float2 h  =
                *reinterpret_cast<const float2*>(H + (size_t)col * HID + 2 * lane);
            ax0 += v * h.x;  ay0 += v * h.y;
        }
        for (int e = s1; e < s1 + d1; ++e) {
            const int   col = colind[e];
            const float v   = vals[e];
            const float2 h  =
                *reinterpret_cast<const float2*>(H + (size_t)col * HID + 2 * lane);
            ax1 += v * h.x;  ay1 += v * h.y;
        }
    }

    Hs[warp][0][2 * lane]     = fmaxf(ax0, 0.f);
    Hs[warp][0][2 * lane + 1] = fmaxf(ay0, 0.f);
    Hs[warp][1][2 * lane]     = fmaxf(ax1, 0.f);
    Hs[warp][1][2 * lane + 1] = fmaxf(ay1, 0.f);
    __syncwarp();

    float ox0 = 0.f, oy0 = 0.f, ox1 = 0.f, oy1 = 0.f;
    #pragma unroll
    for (int j = 0; j < HID; ++j) {
        const float2 w =
            *reinterpret_cast<const float2*>(W2s + j * OUTD + 2 * lane);
        const float a0 = Hs[warp][0][j];
        const float a1 = Hs[warp][1][j];
        ox0 += a0 * w.x;  oy0 += a0 * w.y;
        ox1 += a1 * w.x;  oy1 += a1 * w.y;
    }

    *reinterpret_cast<float2*>(O + (size_t)row0 * OUTD + 2 * lane) =
        make_float2(ox0, oy0);
    if (row1 < NROWS)
        *reinterpret_cast<float2*>(O + (size_t)row1 * OUTD + 2 * lane) =
            make_float2(ox1, oy1);
}

// ---------------------------------------------------------------------------
// Kernel 3: out = A @ O   (2 rows per warp)
// ---------------------------------------------------------------------------
__global__ void __launch_bounds__(256) spmm2_kernel(
    const float* __restrict__ O, const float* __restrict__ vals,
    const int* __restrict__ rowptr, const int* __restrict__ colind,
    float* __restrict__ out)
{
    const int tid  = threadIdx.x;
    const int warp = tid >> 5;
    const int lane = tid & 31;
    const int row0 = (blockIdx.x * 8 + warp) * 2;
    const int row1 = row0 + 1;
    if (row0 >= NROWS) return;

    const int s0 = rowptr[row0];
    const int d0 = rowptr[row0 + 1] - s0;
    const int s1 = (row1 < NROWS) ? rowptr[row1] : 0;
    const int d1 = (row1 < NROWS) ? rowptr[row1 + 1] - s1 : 0;

    float ax0 = 0.f, ay0 = 0.f, ax1 = 0.f, ay1 = 0.f;

    if (d0 == 16 && d1 == 16 && s1 == s0 + 16) {
        const int   myc = __ldg(colind + s0 + lane);
        const float myv = __ldg(vals + s0 + lane);
        #pragma unroll
        for (int e = 0; e < 16; ++e) {
            const int   c0 = __shfl_sync(0xffffffffu, myc, e);
            const float v0 = __shfl_sync(0xffffffffu, myv, e);
            const int   c1 = __shfl_sync(0xffffffffu, myc, 16 + e);
            const float v1 = __shfl_sync(0xffffffffu, myv, 16 + e);
            const float2 o0 =
                *reinterpret_cast<const float2*>(O + (size_t)c0 * OUTD + 2 * lane);
            const float2 o1 =
                *reinterpret_cast<const float2*>(O + (size_t)c1 * OUTD + 2 * lane);
            ax0 += v0 * o0.x;  ay0 += v0 * o0.y;
            ax1 += v1 * o1.x;  ay1 += v1 * o1.y;
        }
    } else {
        for (int e = s0; e < s0 + d0; ++e) {
            const int   col = colind[e];
            const float v   = vals[e];
            const float2 o  =
                *reinterpret_cast<const float2*>(O + (size_t)col * OUTD + 2 * lane);
            ax0 += v * o.x;  ay0 += v * o.y;
        }
        for (int e = s1; e < s1 + d1; ++e) {
            const int   col = colind[e];
            const float v   = vals[e];
            const float2 o  =
                *reinterpret_cast<const float2*>(O + (size_t)col * OUTD + 2 * lane);
            ax1 += v * o.x;  ay1 += v * o.y;
        }
    }

    *reinterpret_cast<float2*>(out + (size_t)row0 * OUTD + 2 * lane) =
        make_float2(ax0, ay0);
    if (row1 < NROWS)
        *reinterpret_cast<float2*>(out + (size_t)row1 * OUTD + 2 * lane) =
            make_float2(ax1, ay1);
}

// ---------------------------------------------------------------------------
extern "C" void kernel_launch(void* const* d_in, const int* in_sizes, int n_in,
                              void* d_out, int out_size)
{
    const float* X      = (const float*)d_in[0];
    const float* W1     = (const float*)d_in[1];
    const float* W2     = (const float*)d_in[2];
    const float* vals   = (const float*)d_in[3];
    const int*   rowptr = (const int*)d_in[4];
    const int*   colind = (const int*)d_in[5];
    float*       out    = (float*)d_out;

    float* H; cudaGetSymbolAddress((void**)&H, g_H);
    float* O; cudaGetSymbolAddress((void**)&O, g_O);

    const int smem1 = 2 * 64 * BSTRIDE * sizeof(__nv_bfloat16);  // 67584 B
    static bool attr_set = false;
    if (!attr_set) {
        cudaFuncSetAttribute(gemm1_mma_kernel,
                             cudaFuncAttributeMaxDynamicSharedMemorySize, smem1);
        attr_set = true;
    }

    gemm1_mma_kernel<<<(NROWS + 255) / 256, 256, smem1>>>(X, W1, H);
    spmm_relu_gemm2_kernel<<<(NROWS + 15) / 16, 256>>>(H, W2, vals, rowptr,
                                                       colind, O);
    spmm2_kernel<<<(NROWS + 15) / 16, 256>>>(O, vals, rowptr, colind, out);
}

// round 9
// speedup vs baseline: 1.7510x; 1.0973x over previous
#include <cuda_runtime.h>
#include <cuda_bf16.h>
#include <cstdint>

#define NROWS 100000
#define INDIM 256
#define HID   64
#define OUTD  64

// scratch (device globals: no allocation allowed)
__device__ __align__(16) float g_H[(size_t)NROWS * HID];
__device__ __align__(16) float g_O[(size_t)NROWS * OUTD];

// m16n8k16 bf16 MMA, f32 accumulate (baseline PTX, works on .target sm_103)
#define MMA_BF16(c0, c1, c2, c3, a0, a1, a2, a3, b0, b1)                      \
    asm volatile(                                                             \
        "mma.sync.aligned.m16n8k16.row.col.f32.bf16.bf16.f32 "                \
        "{%0,%1,%2,%3}, {%4,%5,%6,%7}, {%8,%9}, {%0,%1,%2,%3};"               \
        : "+f"(c0), "+f"(c1), "+f"(c2), "+f"(c3)                              \
        : "r"(a0), "r"(a1), "r"(a2), "r"(a3), "r"(b0), "r"(b1))

// split a float2 into packed bf16x2 hi + bf16x2 lo (residual)
__device__ __forceinline__ void cvt_split(float2 v, uint32_t& hi, uint32_t& lo) {
    uint32_t h;
    asm("cvt.rn.bf16x2.f32 %0, %1, %2;" : "=r"(h) : "f"(v.y), "f"(v.x));
    const float h0 = __uint_as_float(h << 16);
    const float h1 = __uint_as_float(h & 0xffff0000u);
    const float r0 = v.x - h0;
    const float r1 = v.y - h1;
    uint32_t l;
    asm("cvt.rn.bf16x2.f32 %0, %1, %2;" : "=r"(l) : "f"(r1), "f"(r0));
    hi = h;
    lo = l;
}

#define BSTRIDE 264   // 256 + 8 bf16 padding -> conflict-free B-fragment LDS

// ---------------------------------------------------------------------------
// Kernel 1: H = X @ W1 via warp-level bf16 MMA, split-2 (3 MMAs), f32 accum.
// Block 256 thr = 8 warps x 32 rows = 256-row tile.
// __launch_bounds__(256, 2): cap regs at 128 -> 2 CTAs/SM -> 25% occupancy.
// A fragments double-buffered: LDGs for k-step s+1 issued before MMAs of s.
// ---------------------------------------------------------------------------
__global__ void __launch_bounds__(256, 2) gemm1_mma_kernel(
    const float* __restrict__ X, const float* __restrict__ W1,
    float* __restrict__ H)
{
    extern __shared__ __nv_bfloat16 wsm[];
    __nv_bfloat16* Bhi = wsm;                 // [64][BSTRIDE]
    __nv_bfloat16* Blo = wsm + 64 * BSTRIDE;  // [64][BSTRIDE]

    const int tid = threadIdx.x;

    // convert W1 (k-major [256][64]) -> smem n-major hi/lo
    for (int idx = tid; idx < INDIM * HID; idx += 256) {
        const int k = idx >> 6;
        const int n = idx & 63;
        const float w = W1[idx];
        const __nv_bfloat16 hb = __float2bfloat16(w);
        const float hf = __bfloat162float(hb);
        Bhi[n * BSTRIDE + k] = hb;
        Blo[n * BSTRIDE + k] = __float2bfloat16(w - hf);
    }
    __syncthreads();

    const int warp  = tid >> 5;
    const int lane  = tid & 31;
    const int rbase = blockIdx.x * 256 + warp * 32;
    if (rbase >= NROWS) return;

    const int rq = lane >> 2;         // 0..7
    const int cq = (lane & 3) * 2;    // 0,2,4,6

    // row pointers (clamped; results for clamped rows discarded at store)
    const int r00 = rbase + rq;
    const int r01 = r00 + 8;
    const int r10 = rbase + 16 + rq;
    const int r11 = r10 + 8;
    const float* px[2][2];
    px[0][0] = X + (size_t)min(r00, NROWS - 1) * INDIM;
    px[0][1] = X + (size_t)min(r01, NROWS - 1) * INDIM;
    px[1][0] = X + (size_t)min(r10, NROWS - 1) * INDIM;
    px[1][1] = X + (size_t)min(r11, NROWS - 1) * INDIM;

    float acc[2][8][4];
    #pragma unroll
    for (int m = 0; m < 2; ++m)
        #pragma unroll
        for (int n = 0; n < 8; ++n)
            #pragma unroll
            for (int i = 0; i < 4; ++i) acc[m][n][i] = 0.f;

    float2 fb[2][2][4];   // [buf][m][frag]

    // prime buffer 0 (k-step 0)
    #pragma unroll
    for (int m = 0; m < 2; ++m) {
        fb[0][m][0] = *reinterpret_cast<const float2*>(px[m][0] + cq);
        fb[0][m][1] = *reinterpret_cast<const float2*>(px[m][1] + cq);
        fb[0][m][2] = *reinterpret_cast<const float2*>(px[m][0] + cq + 8);
        fb[0][m][3] = *reinterpret_cast<const float2*>(px[m][1] + cq + 8);
    }

    #pragma unroll
    for (int ks = 0; ks < 16; ++ks) {
        const int cur = ks & 1;
        // prefetch next k-step into the other buffer
        if (ks < 15) {
            const int kb = (ks + 1) * 16;
            #pragma unroll
            for (int m = 0; m < 2; ++m) {
                fb[cur ^ 1][m][0] = *reinterpret_cast<const float2*>(px[m][0] + kb + cq);
                fb[cur ^ 1][m][1] = *reinterpret_cast<const float2*>(px[m][1] + kb + cq);
                fb[cur ^ 1][m][2] = *reinterpret_cast<const float2*>(px[m][0] + kb + cq + 8);
                fb[cur ^ 1][m][3] = *reinterpret_cast<const float2*>(px[m][1] + kb + cq + 8);
            }
        }

        // convert current buffer
        uint32_t ahi[2][4], alo[2][4];
        #pragma unroll
        for (int m = 0; m < 2; ++m) {
            cvt_split(fb[cur][m][0], ahi[m][0], alo[m][0]);
            cvt_split(fb[cur][m][1], ahi[m][1], alo[m][1]);
            cvt_split(fb[cur][m][2], ahi[m][2], alo[m][2]);
            cvt_split(fb[cur][m][3], ahi[m][3], alo[m][3]);
        }

        const int kb = ks * 16;
        #pragma unroll
        for (int n = 0; n < 8; ++n) {
            const int boff = (n * 8 + rq) * BSTRIDE + kb + cq;
            const uint32_t bh0 = *reinterpret_cast<const uint32_t*>(Bhi + boff);
            const uint32_t bh1 = *reinterpret_cast<const uint32_t*>(Bhi + boff + 8);
            const uint32_t bl0 = *reinterpret_cast<const uint32_t*>(Blo + boff);
            const uint32_t bl1 = *reinterpret_cast<const uint32_t*>(Blo + boff + 8);

            #pragma unroll
            for (int m = 0; m < 2; ++m) {
                MMA_BF16(acc[m][n][0], acc[m][n][1], acc[m][n][2], acc[m][n][3],
                         ahi[m][0], ahi[m][1], ahi[m][2], ahi[m][3], bh0, bh1);
                MMA_BF16(acc[m][n][0], acc[m][n][1], acc[m][n][2], acc[m][n][3],
                         ahi[m][0], ahi[m][1], ahi[m][2], ahi[m][3], bl0, bl1);
                MMA_BF16(acc[m][n][0], acc[m][n][1], acc[m][n][2], acc[m][n][3],
                         alo[m][0], alo[m][1], alo[m][2], alo[m][3], bh0, bh1);
            }
        }
    }

    #pragma unroll
    for (int m = 0; m < 2; ++m) {
        const int r0 = rbase + m * 16 + rq;
        const int r1 = r0 + 8;
        #pragma unroll
        for (int n = 0; n < 8; ++n) {
            const int col = n * 8 + cq;
            if (r0 < NROWS)
                *reinterpret_cast<float2*>(H + (size_t)r0 * HID + col) =
                    make_float2(acc[m][n][0], acc[m][n][1]);
            if (r1 < NROWS)
                *reinterpret_cast<float2*>(H + (size_t)r1 * HID + col) =
                    make_float2(acc[m][n][2], acc[m][n][3]);
        }
    }
}

// ---------------------------------------------------------------------------
// Kernel 2 (fused): O = relu(A @ H) @ W2
// 2 rows per warp: one coalesced metadata LDG serves both rows; 32 gathers
// in flight per warp.
// ---------------------------------------------------------------------------
__global__ void __launch_bounds__(256) spmm_relu_gemm2_kernel(
    const float* __restrict__ H, const float* __restrict__ W2,
    const float* __restrict__ vals, const int* __restrict__ rowptr,
    const int* __restrict__ colind, float* __restrict__ O)
{
    __shared__ float W2s[HID * OUTD];
    __shared__ float Hs[8][2][HID];

    const int tid = threadIdx.x;
    {
        const float4* src = reinterpret_cast<const float4*>(W2);
        float4* dst = reinterpret_cast<float4*>(W2s);
        #pragma unroll
        for (int i = tid; i < (HID * OUTD) / 4; i += 256) dst[i] = src[i];
    }
    __syncthreads();

    const int warp = tid >> 5;
    const int lane = tid & 31;
    const int row0 = (blockIdx.x * 8 + warp) * 2;
    const int row1 = row0 + 1;
    if (row0 >= NROWS) return;

    const int s0 = rowptr[row0];
    const int d0 = rowptr[row0 + 1] - s0;
    const int s1 = (row1 < NROWS) ? rowptr[row1] : 0;
    const int d1 = (row1 < NROWS) ? rowptr[row1 + 1] - s1 : 0;

    float ax0 = 0.f, ay0 = 0.f, ax1 = 0.f, ay1 = 0.f;

    if (d0 == 16 && d1 == 16 && s1 == s0 + 16) {
        // contiguous fixed-degree rows: one LDG covers both rows' metadata
        const int   myc = __ldg(colind + s0 + lane);
        const float myv = __ldg(vals + s0 + lane);
        #pragma unroll
        for (int e = 0; e < 16; ++e) {
            const int   c0 = __shfl_sync(0xffffffffu, myc, e);
            const float v0 = __shfl_sync(0xffffffffu, myv, e);
            const int   c1 = __shfl_sync(0xffffffffu, myc, 16 + e);
            const float v1 = __shfl_sync(0xffffffffu, myv, 16 + e);
            const float2 h0 =
                *reinterpret_cast<const float2*>(H + (size_t)c0 * HID + 2 * lane);
            const float2 h1 =
                *reinterpret_cast<const float2*>(H + (size_t)c1 * HID + 2 * lane);
            ax0 += v0 * h0.x;  ay0 += v0 * h0.y;
            ax1 += v1 * h1.x;  ay1 += v1 * h1.y;
        }
    } else {
        for (int e = s0; e < s0 + d0; ++e) {
            const int   col = colind[e];
            const float v   = vals[e];
            const float2 h  =
                *reinterpret_cast<const float2*>(H + (size_t)col * HID + 2 * lane);
            ax0 += v * h.x;  ay0 += v * h.y;
        }
        for (int e = s1; e < s1 + d1; ++e) {
            const int   col = colind[e];
            const float v   = vals[e];
            const float2 h  =
                *reinterpret_cast<const float2*>(H + (size_t)col * HID + 2 * lane);
            ax1 += v * h.x;  ay1 += v * h.y;
        }
    }

    Hs[warp][0][2 * lane]     = fmaxf(ax0, 0.f);
    Hs[warp][0][2 * lane + 1] = fmaxf(ay0, 0.f);
    Hs[warp][1][2 * lane]     = fmaxf(ax1, 0.f);
    Hs[warp][1][2 * lane + 1] = fmaxf(ay1, 0.f);
    __syncwarp();

    float ox0 = 0.f, oy0 = 0.f, ox1 = 0.f, oy1 = 0.f;
    #pragma unroll
    for (int j = 0; j < HID; ++j) {
        const float2 w =
            *reinterpret_cast<const float2*>(W2s + j * OUTD + 2 * lane);
        const float a0 = Hs[warp][0][j];
        const float a1 = Hs[warp][1][j];
        ox0 += a0 * w.x;  oy0 += a0 * w.y;
        ox1 += a1 * w.x;  oy1 += a1 * w.y;
    }

    *reinterpret_cast<float2*>(O + (size_t)row0 * OUTD + 2 * lane) =
        make_float2(ox0, oy0);
    if (row1 < NROWS)
        *reinterpret_cast<float2*>(O + (size_t)row1 * OUTD + 2 * lane) =
            make_float2(ox1, oy1);
}

// ---------------------------------------------------------------------------
// Kernel 3: out = A @ O   (4 rows per warp -> 64 gathers in flight)
// ---------------------------------------------------------------------------
__global__ void __launch_bounds__(256) spmm2_kernel(
    const float* __restrict__ O, const float* __restrict__ vals,
    const int* __restrict__ rowptr, const int* __restrict__ colind,
    float* __restrict__ out)
{
    const int tid  = threadIdx.x;
    const int warp = tid >> 5;
    const int lane = tid & 31;
    const int row0 = (blockIdx.x * 8 + warp) * 4;
    if (row0 >= NROWS) return;

    const int s0   = rowptr[row0];
    const int send = rowptr[min(row0 + 4, NROWS)];
    const int nedg = send - s0;

    float ax[4] = {0.f, 0.f, 0.f, 0.f};
    float ay[4] = {0.f, 0.f, 0.f, 0.f};

    if (nedg == 64) {
        // 4 contiguous deg-16 rows: 2 coalesced metadata LDGs
        const int   c_a = __ldg(colind + s0 + lane);
        const float v_a = __ldg(vals + s0 + lane);
        const int   c_b = __ldg(colind + s0 + 32 + lane);
        const float v_b = __ldg(vals + s0 + 32 + lane);
        #pragma unroll
        for (int e = 0; e < 16; ++e) {
            const int   c0 = __shfl_sync(0xffffffffu, c_a, e);
            const float v0 = __shfl_sync(0xffffffffu, v_a, e);
            const int   c1 = __shfl_sync(0xffffffffu, c_a, 16 + e);
            const float v1 = __shfl_sync(0xffffffffu, v_a, 16 + e);
            const int   c2 = __shfl_sync(0xffffffffu, c_b, e);
            const float v2 = __shfl_sync(0xffffffffu, v_b, e);
            const int   c3 = __shfl_sync(0xffffffffu, c_b, 16 + e);
            const float v3 = __shfl_sync(0xffffffffu, v_b, 16 + e);
            const float2 o0 =
                *reinterpret_cast<const float2*>(O + (size_t)c0 * OUTD + 2 * lane);
            const float2 o1 =
                *reinterpret_cast<const float2*>(O + (size_t)c1 * OUTD + 2 * lane);
            const float2 o2 =
                *reinterpret_cast<const float2*>(O + (size_t)c2 * OUTD + 2 * lane);
            const float2 o3 =
                *reinterpret_cast<const float2*>(O + (size_t)c3 * OUTD + 2 * lane);
            ax[0] += v0 * o0.x;  ay[0] += v0 * o0.y;
            ax[1] += v1 * o1.x;  ay[1] += v1 * o1.y;
            ax[2] += v2 * o2.x;  ay[2] += v2 * o2.y;
            ax[3] += v3 * o3.x;  ay[3] += v3 * o3.y;
        }
        #pragma unroll
        for (int r = 0; r < 4; ++r)
            *reinterpret_cast<float2*>(out + (size_t)(row0 + r) * OUTD + 2 * lane) =
                make_float2(ax[r], ay[r]);
    } else {
        for (int r = 0; r < 4; ++r) {
            const int row = row0 + r;
            if (row >= NROWS) break;
            float bx = 0.f, by = 0.f;
            for (int e = rowptr[row]; e < rowptr[row + 1]; ++e) {
                const int   col = colind[e];
                const float v   = vals[e];
                const float2 o  =
                    *reinterpret_cast<const float2*>(O + (size_t)col * OUTD + 2 * lane);
                bx += v * o.x;  by += v * o.y;
            }
            *reinterpret_cast<float2*>(out + (size_t)row * OUTD + 2 * lane) =
                make_float2(bx, by);
        }
    }
}

// ---------------------------------------------------------------------------
extern "C" void kernel_launch(void* const* d_in, const int* in_sizes, int n_in,
                              void* d_out, int out_size)
{
    const float* X      = (const float*)d_in[0];
    const float* W1     = (const float*)d_in[1];
    const float* W2     = (const float*)d_in[2];
    const float* vals   = (const float*)d_in[3];
    const int*   rowptr = (const int*)d_in[4];
    const int*   colind = (const int*)d_in[5];
    float*       out    = (float*)d_out;

    float* H; cudaGetSymbolAddress((void**)&H, g_H);
    float* O; cudaGetSymbolAddress((void**)&O, g_O);

    const int smem1 = 2 * 64 * BSTRIDE * sizeof(__nv_bfloat16);  // 67584 B
    static bool attr_set = false;
    if (!attr_set) {
        cudaFuncSetAttribute(gemm1_mma_kernel,
                             cudaFuncAttributeMaxDynamicSharedMemorySize, smem1);
        attr_set = true;
    }

    gemm1_mma_kernel<<<(NROWS + 255) / 256, 256, smem1>>>(X, W1, H);
    spmm_relu_gemm2_kernel<<<(NROWS + 15) / 16, 256>>>(H, W2, vals, rowptr,
                                                       colind, O);
    spmm2_kernel<<<(NROWS + 31) / 32, 256>>>(O, vals, rowptr, colind, out);
}

// round 10
// speedup vs baseline: 1.9073x; 1.0892x over previous
#include <cuda_runtime.h>
#include <cuda_bf16.h>
#include <cstdint>

#define NROWS 100000
#define INDIM 256
#define HID   64
#define OUTD  64

// scratch (device globals: no allocation allowed)
__device__ __align__(16) float g_H[(size_t)NROWS * HID];
__device__ __align__(16) float g_O[(size_t)NROWS * OUTD];

// m16n8k16 bf16 MMA, f32 accumulate (baseline PTX, works on .target sm_103)
#define MMA_BF16(c0, c1, c2, c3, a0, a1, a2, a3, b0, b1)                      \
    asm volatile(                                                             \
        "mma.sync.aligned.m16n8k16.row.col.f32.bf16.bf16.f32 "                \
        "{%0,%1,%2,%3}, {%4,%5,%6,%7}, {%8,%9}, {%0,%1,%2,%3};"               \
        : "+f"(c0), "+f"(c1), "+f"(c2), "+f"(c3)                              \
        : "r"(a0), "r"(a1), "r"(a2), "r"(a3), "r"(b0), "r"(b1))

// split a float2 into packed bf16x2 hi + bf16x2 lo (residual)
__device__ __forceinline__ void cvt_split(float2 v, uint32_t& hi, uint32_t& lo) {
    uint32_t h;
    asm("cvt.rn.bf16x2.f32 %0, %1, %2;" : "=r"(h) : "f"(v.y), "f"(v.x));
    const float h0 = __uint_as_float(h << 16);
    const float h1 = __uint_as_float(h & 0xffff0000u);
    const float r0 = v.x - h0;
    const float r1 = v.y - h1;
    uint32_t l;
    asm("cvt.rn.bf16x2.f32 %0, %1, %2;" : "=r"(l) : "f"(r1), "f"(r0));
    hi = h;
    lo = l;
}

#define BSTRIDE 264   // 256 + 8 bf16 padding -> conflict-free B-fragment LDS

// ---------------------------------------------------------------------------
// Kernel 1: H = X @ W1 via warp-level bf16 MMA, split-2 (3 MMAs), f32 accum.
// Block 256 thr = 8 warps x 32 rows = 256-row tile; 2 CTAs/SM.
// ---------------------------------------------------------------------------
__global__ void __launch_bounds__(256, 2) gemm1_mma_kernel(
    const float* __restrict__ X, const float* __restrict__ W1,
    float* __restrict__ H)
{
    extern __shared__ __nv_bfloat16 wsm[];
    __nv_bfloat16* Bhi = wsm;                 // [64][BSTRIDE]
    __nv_bfloat16* Blo = wsm + 64 * BSTRIDE;  // [64][BSTRIDE]

    const int tid = threadIdx.x;

    for (int idx = tid; idx < INDIM * HID; idx += 256) {
        const int k = idx >> 6;
        const int n = idx & 63;
        const float w = W1[idx];
        const __nv_bfloat16 hb = __float2bfloat16(w);
        const float hf = __bfloat162float(hb);
        Bhi[n * BSTRIDE + k] = hb;
        Blo[n * BSTRIDE + k] = __float2bfloat16(w - hf);
    }
    __syncthreads();

    const int warp  = tid >> 5;
    const int lane  = tid & 31;
    const int rbase = blockIdx.x * 256 + warp * 32;
    if (rbase >= NROWS) return;

    const int rq = lane >> 2;
    const int cq = (lane & 3) * 2;

    const int r00 = rbase + rq;
    const int r01 = r00 + 8;
    const int r10 = rbase + 16 + rq;
    const int r11 = r10 + 8;
    const float* px[2][2];
    px[0][0] = X + (size_t)min(r00, NROWS - 1) * INDIM;
    px[0][1] = X + (size_t)min(r01, NROWS - 1) * INDIM;
    px[1][0] = X + (size_t)min(r10, NROWS - 1) * INDIM;
    px[1][1] = X + (size_t)min(r11, NROWS - 1) * INDIM;

    float acc[2][8][4];
    #pragma unroll
    for (int m = 0; m < 2; ++m)
        #pragma unroll
        for (int n = 0; n < 8; ++n)
            #pragma unroll
            for (int i = 0; i < 4; ++i) acc[m][n][i] = 0.f;

    float2 fb[2][2][4];

    #pragma unroll
    for (int m = 0; m < 2; ++m) {
        fb[0][m][0] = *reinterpret_cast<const float2*>(px[m][0] + cq);
        fb[0][m][1] = *reinterpret_cast<const float2*>(px[m][1] + cq);
        fb[0][m][2] = *reinterpret_cast<const float2*>(px[m][0] + cq + 8);
        fb[0][m][3] = *reinterpret_cast<const float2*>(px[m][1] + cq + 8);
    }

    #pragma unroll
    for (int ks = 0; ks < 16; ++ks) {
        const int cur = ks & 1;
        if (ks < 15) {
            const int kb = (ks + 1) * 16;
            #pragma unroll
            for (int m = 0; m < 2; ++m) {
                fb[cur ^ 1][m][0] = *reinterpret_cast<const float2*>(px[m][0] + kb + cq);
                fb[cur ^ 1][m][1] = *reinterpret_cast<const float2*>(px[m][1] + kb + cq);
                fb[cur ^ 1][m][2] = *reinterpret_cast<const float2*>(px[m][0] + kb + cq + 8);
                fb[cur ^ 1][m][3] = *reinterpret_cast<const float2*>(px[m][1] + kb + cq + 8);
            }
        }

        uint32_t ahi[2][4], alo[2][4];
        #pragma unroll
        for (int m = 0; m < 2; ++m) {
            cvt_split(fb[cur][m][0], ahi[m][0], alo[m][0]);
            cvt_split(fb[cur][m][1], ahi[m][1], alo[m][1]);
            cvt_split(fb[cur][m][2], ahi[m][2], alo[m][2]);
            cvt_split(fb[cur][m][3], ahi[m][3], alo[m][3]);
        }

        const int kb = ks * 16;
        #pragma unroll
        for (int n = 0; n < 8; ++n) {
            const int boff = (n * 8 + rq) * BSTRIDE + kb + cq;
            const uint32_t bh0 = *reinterpret_cast<const uint32_t*>(Bhi + boff);
            const uint32_t bh1 = *reinterpret_cast<const uint32_t*>(Bhi + boff + 8);
            const uint32_t bl0 = *reinterpret_cast<const uint32_t*>(Blo + boff);
            const uint32_t bl1 = *reinterpret_cast<const uint32_t*>(Blo + boff + 8);

            #pragma unroll
            for (int m = 0; m < 2; ++m) {
                MMA_BF16(acc[m][n][0], acc[m][n][1], acc[m][n][2], acc[m][n][3],
                         ahi[m][0], ahi[m][1], ahi[m][2], ahi[m][3], bh0, bh1);
                MMA_BF16(acc[m][n][0], acc[m][n][1], acc[m][n][2], acc[m][n][3],
                         ahi[m][0], ahi[m][1], ahi[m][2], ahi[m][3], bl0, bl1);
                MMA_BF16(acc[m][n][0], acc[m][n][1], acc[m][n][2], acc[m][n][3],
                         alo[m][0], alo[m][1], alo[m][2], alo[m][3], bh0, bh1);
            }
        }
    }

    #pragma unroll
    for (int m = 0; m < 2; ++m) {
        const int r0 = rbase + m * 16 + rq;
        const int r1 = r0 + 8;
        #pragma unroll
        for (int n = 0; n < 8; ++n) {
            const int col = n * 8 + cq;
            if (r0 < NROWS)
                *reinterpret_cast<float2*>(H + (size_t)r0 * HID + col) =
                    make_float2(acc[m][n][0], acc[m][n][1]);
            if (r1 < NROWS)
                *reinterpret_cast<float2*>(H + (size_t)r1 * HID + col) =
                    make_float2(acc[m][n][2], acc[m][n][3]);
        }
    }
}

// ---------------------------------------------------------------------------
// Kernel 2 (fused): O = relu(A @ H) @ W2
// 4 rows per warp: 2 coalesced metadata LDGs, 64 gathers in flight.
// ---------------------------------------------------------------------------
__global__ void __launch_bounds__(256) spmm_relu_gemm2_kernel(
    const float* __restrict__ H, const float* __restrict__ W2,
    const float* __restrict__ vals, const int* __restrict__ rowptr,
    const int* __restrict__ colind, float* __restrict__ O)
{
    __shared__ float W2s[HID * OUTD];     // 16KB
    __shared__ float Hs[8][4][HID];       // 8KB

    const int tid = threadIdx.x;
    {
        const float4* src = reinterpret_cast<const float4*>(W2);
        float4* dst = reinterpret_cast<float4*>(W2s);
        #pragma unroll
        for (int i = tid; i < (HID * OUTD) / 4; i += 256) dst[i] = src[i];
    }
    __syncthreads();

    const int warp = tid >> 5;
    const int lane = tid & 31;
    const int row0 = (blockIdx.x * 8 + warp) * 4;
    if (row0 >= NROWS) return;

    const int s0   = rowptr[row0];
    const int send = rowptr[min(row0 + 4, NROWS)];
    const int nedg = send - s0;

    float ax[4] = {0.f, 0.f, 0.f, 0.f};
    float ay[4] = {0.f, 0.f, 0.f, 0.f};
    int nrows = 4;

    if (nedg == 64) {
        const int   c_a = __ldg(colind + s0 + lane);
        const float v_a = __ldg(vals + s0 + lane);
        const int   c_b = __ldg(colind + s0 + 32 + lane);
        const float v_b = __ldg(vals + s0 + 32 + lane);
        #pragma unroll
        for (int e = 0; e < 16; ++e) {
            const int   c0 = __shfl_sync(0xffffffffu, c_a, e);
            const float v0 = __shfl_sync(0xffffffffu, v_a, e);
            const int   c1 = __shfl_sync(0xffffffffu, c_a, 16 + e);
            const float v1 = __shfl_sync(0xffffffffu, v_a, 16 + e);
            const int   c2 = __shfl_sync(0xffffffffu, c_b, e);
            const float v2 = __shfl_sync(0xffffffffu, v_b, e);
            const int   c3 = __shfl_sync(0xffffffffu, c_b, 16 + e);
            const float v3 = __shfl_sync(0xffffffffu, v_b, 16 + e);
            const float2 h0 =
                *reinterpret_cast<const float2*>(H + (size_t)c0 * HID + 2 * lane);
            const float2 h1 =
                *reinterpret_cast<const float2*>(H + (size_t)c1 * HID + 2 * lane);
            const float2 h2 =
                *reinterpret_cast<const float2*>(H + (size_t)c2 * HID + 2 * lane);
            const float2 h3 =
                *reinterpret_cast<const float2*>(H + (size_t)c3 * HID + 2 * lane);
            ax[0] += v0 * h0.x;  ay[0] += v0 * h0.y;
            ax[1] += v1 * h1.x;  ay[1] += v1 * h1.y;
            ax[2] += v2 * h2.x;  ay[2] += v2 * h2.y;
            ax[3] += v3 * h3.x;  ay[3] += v3 * h3.y;
        }
    } else {
        nrows = min(4, NROWS - row0);
        for (int r = 0; r < nrows; ++r) {
            const int row = row0 + r;
            for (int e = rowptr[row]; e < rowptr[row + 1]; ++e) {
                const int   col = colind[e];
                const float v   = vals[e];
                const float2 h  =
                    *reinterpret_cast<const float2*>(H + (size_t)col * HID + 2 * lane);
                ax[r] += v * h.x;  ay[r] += v * h.y;
            }
        }
    }

    #pragma unroll
    for (int r = 0; r < 4; ++r) {
        Hs[warp][r][2 * lane]     = fmaxf(ax[r], 0.f);
        Hs[warp][r][2 * lane + 1] = fmaxf(ay[r], 0.f);
    }
    __syncwarp();

    float ox[4] = {0.f, 0.f, 0.f, 0.f};
    float oy[4] = {0.f, 0.f, 0.f, 0.f};
    #pragma unroll
    for (int j = 0; j < HID; ++j) {
        const float2 w =
            *reinterpret_cast<const float2*>(W2s + j * OUTD + 2 * lane);
        #pragma unroll
        for (int r = 0; r < 4; ++r) {
            const float a = Hs[warp][r][j];
            ox[r] += a * w.x;  oy[r] += a * w.y;
        }
    }

    #pragma unroll
    for (int r = 0; r < 4; ++r) {
        if (r < nrows)
            *reinterpret_cast<float2*>(O + (size_t)(row0 + r) * OUTD + 2 * lane) =
                make_float2(ox[r], oy[r]);
    }
}

// ---------------------------------------------------------------------------
// Kernel 3: out = A @ O   (4 rows per warp -> 64 gathers in flight)
// ---------------------------------------------------------------------------
__global__ void __launch_bounds__(256) spmm2_kernel(
    const float* __restrict__ O, const float* __restrict__ vals,
    const int* __restrict__ rowptr, const int* __restrict__ colind,
    float* __restrict__ out)
{
    const int tid  = threadIdx.x;
    const int warp = tid >> 5;
    const int lane = tid & 31;
    const int row0 = (blockIdx.x * 8 + warp) * 4;
    if (row0 >= NROWS) return;

    const int s0   = rowptr[row0];
    const int send = rowptr[min(row0 + 4, NROWS)];
    const int nedg = send - s0;

    float ax[4] = {0.f, 0.f, 0.f, 0.f};
    float ay[4] = {0.f, 0.f, 0.f, 0.f};

    if (nedg == 64) {
        const int   c_a = __ldg(colind + s0 + lane);
        const float v_a = __ldg(vals + s0 + lane);
        const int   c_b = __ldg(colind + s0 + 32 + lane);
        const float v_b = __ldg(vals + s0 + 32 + lane);
        #pragma unroll
        for (int e = 0; e < 16; ++e) {
            const int   c0 = __shfl_sync(0xffffffffu, c_a, e);
            const float v0 = __shfl_sync(0xffffffffu, v_a, e);
            const int   c1 = __shfl_sync(0xffffffffu, c_a, 16 + e);
            const float v1 = __shfl_sync(0xffffffffu, v_a, 16 + e);
            const int   c2 = __shfl_sync(0xffffffffu, c_b, e);
            const float v2 = __shfl_sync(0xffffffffu, v_b, e);
            const int   c3 = __shfl_sync(0xffffffffu, c_b, 16 + e);
            const float v3 = __shfl_sync(0xffffffffu, v_b, 16 + e);
            const float2 o0 =
                *reinterpret_cast<const float2*>(O + (size_t)c0 * OUTD + 2 * lane);
            const float2 o1 =
                *reinterpret_cast<const float2*>(O + (size_t)c1 * OUTD + 2 * lane);
            const float2 o2 =
                *reinterpret_cast<const float2*>(O + (size_t)c2 * OUTD + 2 * lane);
            const float2 o3 =
                *reinterpret_cast<const float2*>(O + (size_t)c3 * OUTD + 2 * lane);
            ax[0] += v0 * o0.x;  ay[0] += v0 * o0.y;
            ax[1] += v1 * o1.x;  ay[1] += v1 * o1.y;
            ax[2] += v2 * o2.x;  ay[2] += v2 * o2.y;
            ax[3] += v3 * o3.x;  ay[3] += v3 * o3.y;
        }
        #pragma unroll
        for (int r = 0; r < 4; ++r)
            *reinterpret_cast<float2*>(out + (size_t)(row0 + r) * OUTD + 2 * lane) =
                make_float2(ax[r], ay[r]);
    } else {
        for (int r = 0; r < 4; ++r) {
            const int row = row0 + r;
            if (row >= NROWS) break;
            float bx = 0.f, by = 0.f;
            for (int e = rowptr[row]; e < rowptr[row + 1]; ++e) {
                const int   col = colind[e];
                const float v   = vals[e];
                const float2 o  =
                    *reinterpret_cast<const float2*>(O + (size_t)col * OUTD + 2 * lane);
                bx += v * o.x;  by += v * o.y;
            }
            *reinterpret_cast<float2*>(out + (size_t)row * OUTD + 2 * lane) =
                make_float2(bx, by);
        }
    }
}

// ---------------------------------------------------------------------------
extern "C" void kernel_launch(void* const* d_in, const int* in_sizes, int n_in,
                              void* d_out, int out_size)
{
    const float* X      = (const float*)d_in[0];
    const float* W1     = (const float*)d_in[1];
    const float* W2     = (const float*)d_in[2];
    const float* vals   = (const float*)d_in[3];
    const int*   rowptr = (const int*)d_in[4];
    const int*   colind = (const int*)d_in[5];
    float*       out    = (float*)d_out;

    float* H; cudaGetSymbolAddress((void**)&H, g_H);
    float* O; cudaGetSymbolAddress((void**)&O, g_O);

    const int smem1 = 2 * 64 * BSTRIDE * sizeof(__nv_bfloat16);  // 67584 B
    static bool attr_set = false;
    if (!attr_set) {
        cudaFuncSetAttribute(gemm1_mma_kernel,
                             cudaFuncAttributeMaxDynamicSharedMemorySize, smem1);
        attr_set = true;
    }

    gemm1_mma_kernel<<<(NROWS + 255) / 256, 256, smem1>>>(X, W1, H);
    spmm_relu_gemm2_kernel<<<(NROWS + 31) / 32, 256>>>(H, W2, vals, rowptr,
                                                       colind, O);
    spmm2_kernel<<<(NROWS + 31) / 32, 256>>>(O, vals, rowptr, colind, out);
}